// round 11
// baseline (speedup 1.0000x reference)
#include <cuda_runtime.h>
#include <cuda_bf16.h>
#include <math.h>
#include <stdint.h>

#define T_TOK 256
#define H_DIM 1024
#define I_DIM 512
#define E_EXP 32
#define TOPK  8
#define NGRP  8
#define GSZ   4
#define TKG   4

#define SWZB(o) ((o) ^ (((o) >> 3) & 0x70))

// ---------------- helpers ----------------
__device__ __forceinline__ uint32_t smem_u32(const void* p) {
    uint32_t a;
    asm("{ .reg .u64 t; cvta.to.shared.u64 t, %1; cvt.u32.u64 %0, t; }" : "=r"(a) : "l"(p));
    return a;
}

__device__ __forceinline__ void bsplit2(float e0, float e1, uint32_t &h, uint32_t &l) {
    asm("cvt.rn.bf16x2.f32 %0, %1, %2;" : "=r"(h) : "f"(e1), "f"(e0));
    float f0 = __uint_as_float(h << 16);
    float f1 = __uint_as_float(h & 0xFFFF0000u);
    float r0 = e0 - f0, r1 = e1 - f1;
    asm("cvt.rn.bf16x2.f32 %0, %1, %2;" : "=r"(l) : "f"(r1), "f"(r0));
}

__device__ __forceinline__ void ldm4(uint32_t r[4], uint32_t addr) {
    asm volatile("ldmatrix.sync.aligned.m8n8.x4.shared.b16 {%0,%1,%2,%3}, [%4];"
        : "=r"(r[0]), "=r"(r[1]), "=r"(r[2]), "=r"(r[3]) : "r"(addr));
}

__device__ __forceinline__ void mma16816(float d[4], const uint32_t a[4],
                                         uint32_t b0, uint32_t b1) {
    asm volatile("mma.sync.aligned.m16n8k16.row.col.f32.bf16.bf16.f32 "
        "{%0,%1,%2,%3}, {%4,%5,%6,%7}, {%8,%9}, {%0,%1,%2,%3};"
        : "+f"(d[0]), "+f"(d[1]), "+f"(d[2]), "+f"(d[3])
        : "r"(a[0]), "r"(a[1]), "r"(a[2]), "r"(a[3]), "r"(b0), "r"(b1));
}

__device__ __forceinline__ void cpa16(uint32_t dst, const void* src, uint32_t sz) {
    asm volatile("cp.async.cg.shared.global [%0], [%1], 16, %2;"
        :: "r"(dst), "l"(src), "r"(sz) : "memory");
}
#define CPA_COMMIT() asm volatile("cp.async.commit_group;" ::: "memory")
#define CPA_WAIT0()  asm volatile("cp.async.wait_group 0;" ::: "memory")

// ---------------- device scratch ----------------
__device__ int   g_topk_idx[T_TOK * TOPK];
__device__ float g_topk_w[T_TOK * TOPK];
__device__ int   g_cnt[E_EXP];
__device__ int   g_tok[E_EXP * T_TOK];
__device__ int   g_slot[E_EXP * T_TOK];
__device__ float g_wt[E_EXP * T_TOK];
__device__ uint16_t g_xhi[T_TOK * H_DIM];
__device__ uint16_t g_xlo[T_TOK * H_DIM];
__device__ uint16_t g_ahi[T_TOK * TOPK * I_DIM];
__device__ uint16_t g_alo[T_TOK * TOPK * I_DIM];
__device__ float g_ybuf[T_TOK * TOPK * H_DIM];

// work queue
__device__ int g_pairs[E_EXP * 2];   // (e<<2)|mt, mt of 128 rows
__device__ int g_npair;
__device__ int g_ctr;
__device__ int g_rdy[E_EXP * 2];

// ---------------- kernel 1: routing (coalesced GEMV + fused x split) ----------------
__global__ __launch_bounds__(128) void routing_kernel(
    const float* __restrict__ x, const float* __restrict__ gate_w,
    const float* __restrict__ bias)
{
    int t = blockIdx.x;
    __shared__ float xs[H_DIM];
    __shared__ float part[4][E_EXP];
    __shared__ float sc[E_EXP];
    __shared__ float sfc[E_EXP];
    int tid = threadIdx.x;
    for (int i = tid; i < H_DIM / 4; i += 128) {
        float4 v = *(const float4*)(x + (size_t)t * H_DIM + i * 4);
        *(float4*)&xs[i * 4] = v;
        uint32_t h0, l0, h1, l1;
        bsplit2(v.x, v.y, h0, l0);
        bsplit2(v.z, v.w, h1, l1);
        ((uint2*)(g_xhi + (size_t)t * H_DIM))[i] = make_uint2(h0, h1);
        ((uint2*)(g_xlo + (size_t)t * H_DIM))[i] = make_uint2(l0, l1);
    }
    __syncthreads();
    int warp = tid >> 5, lane = tid & 31;
    {
        float s = 0.f;
        const float* gw = gate_w + lane;
        int h0 = warp * (H_DIM / 4);
        #pragma unroll 4
        for (int h = h0; h < h0 + H_DIM / 4; h++)
            s += xs[h] * gw[(size_t)h * E_EXP];
        part[warp][lane] = s;
    }
    __syncthreads();
    if (tid < E_EXP) {
        float s = part[0][tid] + part[1][tid] + part[2][tid] + part[3][tid];
        float sig = 1.f / (1.f + expf(-s));
        sc[tid] = sig;
        sfc[tid] = sig + bias[tid];
    }
    __syncthreads();
    if (tid == 0) {
        float gs[NGRP];
        #pragma unroll
        for (int g = 0; g < NGRP; g++) {
            float m1 = -1e30f, m2 = -1e30f;
            #pragma unroll
            for (int j = 0; j < GSZ; j++) {
                float v = sfc[g * GSZ + j];
                if (v > m1) { m2 = m1; m1 = v; }
                else if (v > m2) { m2 = v; }
            }
            gs[g] = m1 + m2;
        }
        bool gsel[NGRP];
        #pragma unroll
        for (int g = 0; g < NGRP; g++) gsel[g] = false;
        for (int r = 0; r < TKG; r++) {
            int b = -1;
            for (int g = 0; g < NGRP; g++)
                if (!gsel[g] && (b < 0 || gs[g] > gs[b])) b = g;
            gsel[b] = true;
        }
        float masked[E_EXP];
        bool used[E_EXP];
        #pragma unroll
        for (int e = 0; e < E_EXP; e++) {
            masked[e] = gsel[e >> 2] ? sfc[e] : 0.0f;
            used[e] = false;
        }
        int idx[TOPK];
        float wsum = 0.f;
        for (int r = 0; r < TOPK; r++) {
            int b = -1;
            for (int e = 0; e < E_EXP; e++)
                if (!used[e] && (b < 0 || masked[e] > masked[b])) b = e;
            used[b] = true;
            idx[r] = b;
            wsum += sc[b];
        }
        float scale = 2.5f / (wsum + 1e-20f);
        for (int r = 0; r < TOPK; r++) {
            g_topk_idx[t * TOPK + r] = idx[r];
            g_topk_w[t * TOPK + r]   = sc[idx[r]] * scale;
        }
    }
}

// ---------------- kernel 2: compaction + work-queue setup ----------------
__global__ __launch_bounds__(1024) void build_lists_kernel()
{
    int e = threadIdx.x >> 5;
    int lane = threadIdx.x & 31;
    int cnt = 0;
    for (int t0 = 0; t0 < T_TOK; t0 += 32) {
        int t = t0 + lane;
        int found = -1;
        #pragma unroll
        for (int k = 0; k < TOPK; k++)
            if (g_topk_idx[t * TOPK + k] == e) found = k;
        unsigned m = __ballot_sync(0xffffffffu, found >= 0);
        if (found >= 0) {
            int pos = cnt + __popc(m & ((1u << lane) - 1));
            g_tok [e * T_TOK + pos] = t;
            g_slot[e * T_TOK + pos] = found;
            g_wt  [e * T_TOK + pos] = g_topk_w[t * TOPK + found];
        }
        cnt += __popc(m);
    }
    if (lane == 0) g_cnt[e] = cnt;
    if (threadIdx.x < E_EXP * 2) g_rdy[threadIdx.x] = 0;
    __syncthreads();
    if (threadIdx.x == 0) {
        int n = 0;
        for (int ee = 0; ee < E_EXP; ee++) {
            int c = g_cnt[ee];
            for (int mt = 0; mt * 128 < c; mt++) g_pairs[n++] = (ee << 2) | mt;
        }
        g_npair = n;
        g_ctr = 0;
    }
}

// ---------------- fused persistent GEMM kernel ----------------
// CTA tile 128m x 128n, 512 threads, warp tile 32x32 (wm=w>>2, wn=w&3), K chunk 64.
// smem (160KB): A [0,64K): buf{hi 16K, lo 16K} x2; B bf16 [64K,96K): {BH 16K, BL 16K};
// W fp32 stage [96K,160K): {S0 32K, S1 32K}.
// Queue: [0, npair*8) gateup (nt: I/64, B = g||u); [npair*8, npair*16) down (nt: H/128).

__global__ __launch_bounds__(512, 1) void moe_gemm_kernel(
    const float* __restrict__ Wg,
    const float* __restrict__ Wu,
    const float* __restrict__ Wd)
{
    extern __shared__ __align__(128) char dsm[];
    __shared__ int   s_widx;
    __shared__ int   s_toks[128];
    __shared__ int   s_rids[128];
    __shared__ float s_wts[128];

    int tid = threadIdx.x;
    int lane = tid & 31;
    int w = tid >> 5;
    int wm = w >> 2;   // 0..3 (m frag group)
    int wn = w & 3;    // 0..3 (n strip), spread across SMSPs

    uint32_t uA = smem_u32(dsm);
    uint32_t uBhB = uA + 65536;
    uint32_t uBlB = uA + 81920;
    uint32_t uStage = uA + 98304;

    // A cp.async addressing: row = tid>>2, two 16B segs
    int arow = tid >> 2, aseg = tid & 3;
    uint32_t dOa0 = SWZB((uint32_t)(arow * 128 + aseg * 16));
    uint32_t dOa1 = SWZB((uint32_t)(arow * 128 + aseg * 16 + 64));

    // weight stage cp.async: row(k) = tid>>3, 4x16B at (tid&7)*64
    int srow = tid >> 3, sseg = tid & 7;
    uint32_t stDst = (uint32_t)(srow * 512 + sseg * 64);

    // conversion indices
    int pn = tid & 127, pkb = tid >> 7;   // pn: n col, pkb: 0..3

    // ldmatrix addressing
    int aRow = wm * 32 + (lane & 15);
    uint32_t aKb = (uint32_t)((lane >> 4) * 16);
    int bRow = wn * 32 + (lane & 7) + ((lane >> 4) << 3);
    uint32_t bKb = (uint32_t)(((lane >> 3) & 1) * 16);

    int lr = lane >> 2, lc = (lane & 3) * 2;

    for (;;) {
        __syncthreads();
        if (tid == 0) s_widx = atomicAdd(&g_ctr, 1);
        __syncthreads();
        int widx = s_widx;
        int npair = g_npair;
        if (widx >= npair * 16) return;

        bool isGate = (widx < npair * 8);
        int w2 = isGate ? widx : widx - npair * 8;
        int pidx = w2 >> 3;
        int nt = w2 & 7;
        int pr = g_pairs[pidx];
        int e = pr >> 2, mt = pr & 3;
        int ne = g_cnt[e];
        int m0 = mt * 128;

        if (!isGate && tid == 0) {
            while (atomicAdd(&g_rdy[pidx], 0) < 8) { }
        }
        if (tid < 128) {
            int i = m0 + tid;
            if (i < ne) {
                int tk = g_tok[e * T_TOK + i];
                s_toks[tid] = tk;
                s_rids[tid] = tk * TOPK + g_slot[e * T_TOK + i];
                s_wts[tid]  = g_wt[e * T_TOK + i];
            } else { s_toks[tid] = -1; s_rids[tid] = -1; s_wts[tid] = 0.f; }
        }
        __syncthreads();

        // per-fragment activity (skip all-padding 16-row frags)
        bool act0 = (m0 + wm * 32) < ne;
        bool act1 = (m0 + wm * 32 + 16) < ne;

        // A source
        const char *sHi, *sLo;
        uint32_t szA;
        if (isGate) {
            int tok = s_toks[arow];
            sHi = (const char*)g_xhi + ((size_t)(tok < 0 ? 0 : tok) * H_DIM) * 2 + aseg * 16;
            sLo = (const char*)g_xlo + ((size_t)(tok < 0 ? 0 : tok) * H_DIM) * 2 + aseg * 16;
            szA = (tok >= 0) ? 16u : 0u;
        } else {
            int rid = s_rids[arow];
            sHi = (const char*)g_ahi + ((size_t)(rid < 0 ? 0 : rid) * I_DIM) * 2 + aseg * 16;
            sLo = (const char*)g_alo + ((size_t)(rid < 0 ? 0 : rid) * I_DIM) * 2 + aseg * 16;
            szA = (s_rids[arow] >= 0) ? 16u : 0u;
        }

        // weight stage source (fp32), per-chunk stride in floats
        const float* sW;
        size_t wStride;
        if (isGate) {
            const float* wgB = Wg + (size_t)e * H_DIM * I_DIM + nt * 64;
            const float* wuB = Wu + (size_t)e * H_DIM * I_DIM + nt * 64;
            sW = (sseg < 4) ? (wgB + (size_t)srow * I_DIM + sseg * 16)
                            : (wuB + (size_t)srow * I_DIM + (sseg - 4) * 16);
            wStride = (size_t)64 * I_DIM;
        } else {
            const float* wdB = Wd + (size_t)e * I_DIM * H_DIM + nt * 128;
            sW = wdB + (size_t)srow * H_DIM + sseg * 16;
            wStride = (size_t)64 * H_DIM;
        }

        float acc[2][4][4];
        #pragma unroll
        for (int a = 0; a < 2; a++)
            #pragma unroll
            for (int b = 0; b < 4; b++)
                #pragma unroll
                for (int c = 0; c < 4; c++) acc[a][b][c] = 0.f;

        // prologue: A(0) + stage(0)
        cpa16(uA + dOa0, sHi, szA);
        cpa16(uA + dOa1, sHi + 64, szA);
        cpa16(uA + 16384 + dOa0, sLo, szA);
        cpa16(uA + 16384 + dOa1, sLo + 64, szA);
        #pragma unroll
        for (int q = 0; q < 4; q++)
            cpa16(uStage + stDst + q * 16, sW + q * 4, 16);
        CPA_COMMIT();

        const int NCH = isGate ? (H_DIM / 64) : (I_DIM / 64);
        for (int ch = 0; ch < NCH; ch++) {
            CPA_WAIT0();
            __syncthreads();   // cross-thread cp.async visibility
            // convert stage fp32 -> B bf16 hi/lo
            {
                const float* stgW = (const float*)(dsm + 98304 + (ch & 1) * 32768);
                #pragma unroll
                for (int it = 0; it < 4; it++) {
                    int kb4 = (pkb + it * 4) * 4;
                    float c0 = stgW[(kb4 + 0) * 128 + pn];
                    float c1 = stgW[(kb4 + 1) * 128 + pn];
                    float c2 = stgW[(kb4 + 2) * 128 + pn];
                    float c3 = stgW[(kb4 + 3) * 128 + pn];
                    uint32_t h01, l01, h23, l23;
                    bsplit2(c0, c1, h01, l01);
                    bsplit2(c2, c3, h23, l23);
                    uint32_t o = SWZB((uint32_t)(pn * 128 + (pkb + it * 4) * 8));
                    *(uint2*)(dsm + 65536 + o) = make_uint2(h01, h23);
                    *(uint2*)(dsm + 81920 + o) = make_uint2(l01, l23);
                }
            }
            __syncthreads();

            if (ch + 1 < NCH) {
                uint32_t ab = uA + (uint32_t)(((ch + 1) & 1) * 32768);
                uint32_t boff = (uint32_t)((ch + 1) * 128);
                cpa16(ab + dOa0, sHi + boff, szA);
                cpa16(ab + dOa1, sHi + boff + 64, szA);
                cpa16(ab + 16384 + dOa0, sLo + boff, szA);
                cpa16(ab + 16384 + dOa1, sLo + boff + 64, szA);
                uint32_t sb = uStage + (uint32_t)(((ch + 1) & 1) * 32768);
                const float* ws = sW + (size_t)(ch + 1) * wStride;
                #pragma unroll
                for (int q = 0; q < 4; q++)
                    cpa16(sb + stDst + q * 16, ws + q * 4, 16);
                CPA_COMMIT();
            }

            if (act0) {
                uint32_t uAhi = uA + (uint32_t)((ch & 1) * 32768);
                uint32_t uAlo = uAhi + 16384;
                #pragma unroll
                for (int ks = 0; ks < 4; ks++) {
                    uint32_t ah[2][4], al[2][4];
                    {
                        uint32_t o = SWZB((uint32_t)(aRow * 128) + (uint32_t)(ks * 32) + aKb);
                        ldm4(ah[0], uAhi + o);
                        ldm4(al[0], uAlo + o);
                    }
                    if (act1) {
                        uint32_t o = SWZB((uint32_t)((aRow + 16) * 128) + (uint32_t)(ks * 32) + aKb);
                        ldm4(ah[1], uAhi + o);
                        ldm4(al[1], uAlo + o);
                    }
                    uint32_t ob1 = SWZB((uint32_t)(bRow * 128) + (uint32_t)(ks * 32) + bKb);
                    uint32_t ob2 = SWZB((uint32_t)((bRow + 16) * 128) + (uint32_t)(ks * 32) + bKb);
                    uint32_t bh[8], bl[8];
                    ldm4(bh, uBhB + ob1);
                    ldm4(bh + 4, uBhB + ob2);
                    ldm4(bl, uBlB + ob1);
                    ldm4(bl + 4, uBlB + ob2);
                    #pragma unroll
                    for (int nf = 0; nf < 4; nf++) {
                        mma16816(acc[0][nf], ah[0], bh[nf * 2], bh[nf * 2 + 1]);
                        mma16816(acc[0][nf], ah[0], bl[nf * 2], bl[nf * 2 + 1]);
                        mma16816(acc[0][nf], al[0], bh[nf * 2], bh[nf * 2 + 1]);
                    }
                    if (act1) {
                        #pragma unroll
                        for (int nf = 0; nf < 4; nf++) {
                            mma16816(acc[1][nf], ah[1], bh[nf * 2], bh[nf * 2 + 1]);
                            mma16816(acc[1][nf], ah[1], bl[nf * 2], bl[nf * 2 + 1]);
                            mma16816(acc[1][nf], al[1], bh[nf * 2], bh[nf * 2 + 1]);
                        }
                    }
                }
            }
            __syncthreads();
        }

        if (isGate) {
            // stage accs as fp32 [128][128] in A region (64KB), then silu(g)*u
            float* stg = (float*)dsm;
            #pragma unroll
            for (int mf = 0; mf < 2; mf++) {
                #pragma unroll
                for (int nf = 0; nf < 4; nf++) {
                    int col = wn * 32 + nf * 8 + lc;
                    #pragma unroll
                    for (int half = 0; half < 2; half++) {
                        int row = wm * 32 + mf * 16 + lr + half * 8;
                        *(float2*)&stg[row * 128 + col] =
                            make_float2(acc[mf][nf][half * 2], acc[mf][nf][half * 2 + 1]);
                    }
                }
            }
            __syncthreads();
            #pragma unroll
            for (int p = 0; p < 8; p++) {
                int idx2 = tid + p * 512;      // 4096 = 128 rows x 32 col-pairs
                int row = idx2 >> 5;
                int cp = idx2 & 31;
                int rid = s_rids[row];
                if (rid >= 0) {
                    float2 g = *(float2*)&stg[row * 128 + cp * 2];
                    float2 u = *(float2*)&stg[row * 128 + 64 + cp * 2];
                    float a0 = (g.x / (1.f + expf(-g.x))) * u.x;
                    float a1 = (g.y / (1.f + expf(-g.y))) * u.y;
                    uint32_t h, l;
                    bsplit2(a0, a1, h, l);
                    size_t off = (size_t)rid * I_DIM + nt * 64 + cp * 2;
                    *(uint32_t*)(g_ahi + off) = h;
                    *(uint32_t*)(g_alo + off) = l;
                }
            }
            __threadfence();
            __syncthreads();
            if (tid == 0) atomicAdd(&g_rdy[pidx], 1);
        } else {
            #pragma unroll
            for (int mf = 0; mf < 2; mf++) {
                #pragma unroll
                for (int nf = 0; nf < 4; nf++) {
                    int col = nt * 128 + wn * 32 + nf * 8 + lc;
                    #pragma unroll
                    for (int half = 0; half < 2; half++) {
                        int row = wm * 32 + mf * 16 + lr + half * 8;
                        if (m0 + row < ne) {
                            int rid = s_rids[row];
                            float wt = s_wts[row];
                            float2 o;
                            o.x = wt * acc[mf][nf][half * 2 + 0];
                            o.y = wt * acc[mf][nf][half * 2 + 1];
                            *(float2*)(g_ybuf + (size_t)rid * H_DIM + col) = o;
                        }
                    }
                }
            }
        }
    }
}

// ---------------- kernel: deterministic combine ----------------
__global__ __launch_bounds__(256) void combine_kernel(float* __restrict__ out)
{
    int idx = blockIdx.x * 256 + threadIdx.x;
    int t = idx >> 10;
    int h = idx & 1023;
    float s = 0.f;
    #pragma unroll
    for (int k = 0; k < TOPK; k++)
        s += g_ybuf[((size_t)t * TOPK + k) * H_DIM + h];
    out[idx] = s;
}

// ---------------- launch ----------------
#define GEMM_SMEM (64 * 1024 + 32 * 1024 + 64 * 1024)   // 160KB
#define N_PERSIST 148

extern "C" void kernel_launch(void* const* d_in, const int* in_sizes, int n_in,
                              void* d_out, int out_size)
{
    const float* x      = (const float*)d_in[0];
    const float* gate_w = (const float*)d_in[1];
    const float* bias   = (const float*)d_in[2];
    const float* Wg     = (const float*)d_in[3];
    const float* Wu     = (const float*)d_in[4];
    const float* Wd     = (const float*)d_in[5];
    float* out = (float*)d_out;

    cudaFuncSetAttribute(moe_gemm_kernel, cudaFuncAttributeMaxDynamicSharedMemorySize, GEMM_SMEM);

    routing_kernel<<<T_TOK, 128>>>(x, gate_w, bias);
    build_lists_kernel<<<1, 1024>>>();
    moe_gemm_kernel<<<N_PERSIST, 512, GEMM_SMEM>>>(Wg, Wu, Wd);
    combine_kernel<<<(T_TOK * H_DIM) / 256, 256>>>(out);
}